// round 9
// baseline (speedup 1.0000x reference)
#include <cuda_runtime.h>
#include <cuda_fp16.h>
#include <cstdint>

#define NB   1024
#define NP   9
#define ND   2700
#define NDP  2720                /* ND padded to 32-multiple */
#define NDFF 512
#define NM   (NB * NP)
#define TEPS 1e-5f
#define MDSZ ((size_t)NM * (size_t)ND)

/* ---------------- scratch (device statics; no allocs) ---------------- */
__device__ float  g_mod[3ULL * NM * ND];
__device__ float  g_qkv[3ULL * NM * ND];
__device__ __half g_Xh [(size_t)NM * NDP];     /* X -> fp16, K-padded        */
__device__ __half g_H1h[(size_t)NM * NDFF];
__device__ __half g_H2h[(size_t)NM * NDFF];
__device__ __half g_Wth[3ULL * ND * NDP];      /* W^T  fp16 (n-major, K-pad) */
__device__ __half g_WCth[6ULL * ND * NDFF];    /* WC^T fp16                  */

struct MainP  { const float* W[3]; const float* bias[3]; };
struct AuxP   { const float* WC1[3]; const float* WC2[3]; const float* bC1[3]; const float* bC2[3]; };
struct TransP { const float* src[9]; };        /* W q,k,v then WC1 q,k,v then WC2 q,k,v */

/* ---------------- helpers ---------------- */
__device__ __forceinline__ uint32_t smem_u32(const void* p) {
    uint32_t a;
    asm("{ .reg .u64 t; cvta.to.shared.u64 t, %1; cvt.u32.u64 %0, t; }" : "=r"(a) : "l"(p));
    return a;
}
__device__ __forceinline__ void cp_async16(uint32_t dst, const void* src) {
    asm volatile("cp.async.cg.shared.global [%0], [%1], 16;"
                 :: "r"(dst), "l"(src) : "memory");
}
#define CP_COMMIT() asm volatile("cp.async.commit_group;" ::: "memory")
#define CP_WAITG()  asm volatile("cp.async.wait_group 1;" ::: "memory")

#define MMA_F16(c, a0, a1, a2, a3, b0, b1)                                            \
    asm volatile("mma.sync.aligned.m16n8k16.row.col.f32.f16.f16.f32 "                 \
        "{%0,%1,%2,%3}, {%4,%5,%6,%7}, {%8,%9}, {%0,%1,%2,%3};"                       \
        : "+f"((c)[0]), "+f"((c)[1]), "+f"((c)[2]), "+f"((c)[3])                      \
        : "r"(a0), "r"(a1), "r"(a2), "r"(a3), "r"(b0), "r"(b1))

__device__ __forceinline__ void ldsm4(uint32_t& r0, uint32_t& r1, uint32_t& r2,
                                      uint32_t& r3, uint32_t addr) {
    asm volatile("ldmatrix.sync.aligned.m8n8.x4.shared.b16 {%0,%1,%2,%3}, [%4];"
                 : "=r"(r0), "=r"(r1), "=r"(r2), "=r"(r3) : "r"(addr));
}

/* smem tile: 128 rows x 40 halfs stride (32 data + 8 pad) = 80 B/row.
 * LDSM 8-lane phases: row stride 20 b32 -> (r*20) mod 32 covers all banks. */
#define ROWB   80                        /* bytes per row          */
#define TILEB  (128 * ROWB)              /* 10240 B                */
#define STAGEB (2 * TILEB)               /* A + B: 20480 B         */
#define NSTAGE 3
#define SMEM_BYTES (NSTAGE * STAGEB)     /* 61440 B                */

/* ================= prep kernels (2 launches) ================= */
/* z=0: X (pad ND->NDP), z=1: H1, z=2: H2 */
__global__ void prep_act(const float* __restrict__ X, const float* __restrict__ H1,
                         const float* __restrict__ H2, __half* __restrict__ xh,
                         __half* __restrict__ h1h, __half* __restrict__ h2h)
{
    const int z = blockIdx.z;
    const float* in; __half* out; int C, CP;
    if (z == 0)      { in = X;  out = xh;  C = ND;   CP = NDP;  }
    else if (z == 1) { in = H1; out = h1h; C = NDFF; CP = NDFF; }
    else             { in = H2; out = h2h; C = NDFF; CP = NDFF; }
    const int nb = CP / 8;
    const int idx = blockIdx.x * blockDim.x + threadIdx.x;
    if (idx >= NM * nb) return;
    const int row = idx / nb, c0 = (idx % nb) * 8;
    const float* ip = in + (size_t)row * C + c0;
    __half h[8];
    if (c0 + 8 <= C) {
        const float4 v0 = *(const float4*)ip;
        const float4 v1 = *(const float4*)(ip + 4);
        h[0] = __float2half_rn(v0.x); h[1] = __float2half_rn(v0.y);
        h[2] = __float2half_rn(v0.z); h[3] = __float2half_rn(v0.w);
        h[4] = __float2half_rn(v1.x); h[5] = __float2half_rn(v1.y);
        h[6] = __float2half_rn(v1.z); h[7] = __float2half_rn(v1.w);
    } else {
#pragma unroll
        for (int q = 0; q < 8; q++)
            h[q] = (c0 + q < C) ? __float2half_rn(ip[q]) : __float2half_rn(0.f);
    }
    *(uint4*)(out + (size_t)row * CP + c0) = *(const uint4*)h;
}

/* transpose + fp16: z<3: W (2700x2700 -> 2700x2720); z>=3: WC (512x2700 -> 2700x512) */
__global__ void trans_all(TransP tp, __half* __restrict__ wth, __half* __restrict__ wcth)
{
    __shared__ float t[32][33];
    const int z = blockIdx.z;
    int R, RP; __half* dst;
    if (z < 3) { R = ND;   RP = NDP;  dst = wth  + (size_t)z * ND * NDP; }
    else       { R = NDFF; RP = NDFF; dst = wcth + (size_t)(z - 3) * ND * NDFF; }
    const int r0 = blockIdx.y * 32;
    if (r0 >= R) return;
    const float* src = tp.src[z];
    const int c0 = blockIdx.x * 32;
    const int x = threadIdx.x, y = threadIdx.y;    /* 32 x 8 */
#pragma unroll
    for (int yy = y; yy < 32; yy += 8) {
        const int r = r0 + yy, c = c0 + x;
        t[yy][x] = (r < R && c < ND) ? src[(size_t)r * ND + c] : 0.f;
    }
    __syncthreads();
#pragma unroll
    for (int yy = y; yy < 32; yy += 8) {
        const int c = c0 + yy;
        if (c < ND && r0 + x < R)
            dst[(size_t)c * RP + r0 + x] = __float2half_rn(t[x][yy]);
    }
}

/* ================= GEMM mainloop pieces ================= */
/* thread t owns row t of both tiles; 32 halfs = 64 B = 4x cp.async16 */
__device__ __forceinline__ void load_tile(const __half* Arow, const __half* Brow,
                                          uint32_t stage, int tid)
{
    const uint32_t ra = stage + (uint32_t)tid * ROWB;
    const uint32_t rb = ra + TILEB;
#pragma unroll
    for (int q = 0; q < 4; q++) {
        cp_async16(ra + q * 16, Arow + q * 8);
        cp_async16(rb + q * 16, Brow + q * 8);
    }
}

/* ldmatrix-based fragment load + MMA for one K=32 chunk.
 * B fragments loaded first (16 regs), A loaded per-ii (4 regs live) to keep
 * peak registers under the 3-CTA/SM budget.                                 */
__device__ __forceinline__ void chunk_mma(uint32_t aTile, uint32_t bTile,
                                          int mw, int nw, int lane,
                                          float acc[4][8][4])
{
    const uint32_t aBase = aTile +
        (uint32_t)((mw + (lane & 15)) * ROWB + (lane >> 4) * 16);
    const uint32_t bBase = bTile +
        (uint32_t)((nw + (lane & 7) + ((lane & 16) ? 8 : 0)) * ROWB + ((lane >> 3) & 1) * 16);
#pragma unroll
    for (int ks = 0; ks < 2; ks++) {
        uint32_t b[8][2];
#pragma unroll
        for (int jp = 0; jp < 4; jp++)
            ldsm4(b[2 * jp][0], b[2 * jp][1], b[2 * jp + 1][0], b[2 * jp + 1][1],
                  bBase + jp * (16 * ROWB) + ks * 32);
#pragma unroll
        for (int ii = 0; ii < 4; ii++) {
            uint32_t a0, a1, a2, a3;
            ldsm4(a0, a1, a2, a3, aBase + ii * (16 * ROWB) + ks * 32);
#pragma unroll
            for (int jj = 0; jj < 8; jj++)
                MMA_F16(acc[ii][jj], a0, a1, a2, a3, b[jj][0], b[jj][1]);
        }
    }
}

/* ---------------- main GEMM: qkv = (X @ W + b) * mod ----------------- */
__global__ __launch_bounds__(128, 3)
void main_tc(const __half* __restrict__ Xh, const __half* __restrict__ Wall, MainP p)
{
    extern __shared__ __align__(16) uint32_t shu[];
    const uint32_t sbase = smem_u32(shu);
    const int tid = threadIdx.x, lane = tid & 31, wid = tid >> 5;
    const int g = lane >> 2, t = lane & 3;
    const int mw = (wid & 1) * 64, nw = (wid >> 1) * 64;
    const int zi = blockIdx.z, n0 = blockIdx.x * 128, m0 = blockIdx.y * 128;
    const __half* Wt = Wall + (size_t)zi * ND * NDP;
    const int NC = NDP / 32;                     /* 85 */
    const int nrow = n0 + tid;
    const __half* Arow0 = Xh + (size_t)(m0 + tid) * NDP;
    const __half* Brow0 = Wt + (size_t)(nrow < ND ? nrow : 0) * NDP;

    float acc[4][8][4];
#pragma unroll
    for (int i = 0; i < 4; i++)
#pragma unroll
        for (int j = 0; j < 8; j++)
#pragma unroll
            for (int q = 0; q < 4; q++) acc[i][j][q] = 0.f;

#pragma unroll
    for (int c = 0; c < 2; c++) {
        load_tile(Arow0 + c * 32, Brow0 + c * 32, sbase + c * STAGEB, tid);
        CP_COMMIT();
    }

    for (int i = 0; i < NC; i++) {
        const int s = i % NSTAGE;
        CP_WAITG();
        __syncthreads();
        const int j = i + 2;
        if (j < NC)
            load_tile(Arow0 + j * 32, Brow0 + j * 32,
                      sbase + (uint32_t)(j % NSTAGE) * STAGEB, tid);
        CP_COMMIT();
        const uint32_t st = sbase + (uint32_t)s * STAGEB;
        chunk_mma(st, st + TILEB, mw, nw, lane, acc);
    }

    const float* bias = p.bias[zi];
#pragma unroll
    for (int ii = 0; ii < 4; ii++) {
#pragma unroll
        for (int half = 0; half < 2; half++) {
            const int m = m0 + mw + ii * 16 + g + half * 8;
            float* dst = g_qkv + (size_t)zi * MDSZ + (size_t)m * ND;
            const float* modp = g_mod + (size_t)zi * MDSZ + (size_t)m * ND;
#pragma unroll
            for (int jj = 0; jj < 8; jj++) {
                const int n = n0 + nw + jj * 8 + t * 2;
                if (n < ND)     dst[n]     = (acc[ii][jj][half * 2]     + bias[n])     * modp[n];
                if (n + 1 < ND) dst[n + 1] = (acc[ii][jj][half * 2 + 1] + bias[n + 1]) * modp[n + 1];
            }
        }
    }
}

/* ---------------- aux GEMM: mod = H1@WC1 + H2@WC2 + bC1 + bC2 -------- */
__global__ __launch_bounds__(128, 3)
void aux_tc(const __half* __restrict__ H1h, const __half* __restrict__ H2h,
            const __half* __restrict__ WCall, AuxP p)
{
    extern __shared__ __align__(16) uint32_t shu[];
    const uint32_t sbase = smem_u32(shu);
    const int tid = threadIdx.x, lane = tid & 31, wid = tid >> 5;
    const int g = lane >> 2, t = lane & 3;
    const int mw = (wid & 1) * 64, nw = (wid >> 1) * 64;
    const int zi = blockIdx.z, n0 = blockIdx.x * 128, m0 = blockIdx.y * 128;
    const __half* W1t = WCall + (size_t)zi * ND * NDFF;
    const __half* W2t = WCall + (size_t)(zi + 3) * ND * NDFF;
    const int NC = 32;
    const int nrow = n0 + tid;
    const int nsafe = (nrow < ND) ? nrow : 0;

    float acc[4][8][4];
#pragma unroll
    for (int i = 0; i < 4; i++)
#pragma unroll
        for (int j = 0; j < 8; j++)
#pragma unroll
            for (int q = 0; q < 4; q++) acc[i][j][q] = 0.f;

#pragma unroll
    for (int c = 0; c < 2; c++) {
        load_tile(H1h + (size_t)(m0 + tid) * NDFF + c * 32,
                  W1t + (size_t)nsafe * NDFF + c * 32, sbase + c * STAGEB, tid);
        CP_COMMIT();
    }

    for (int i = 0; i < NC; i++) {
        const int s = i % NSTAGE;
        CP_WAITG();
        __syncthreads();
        const int j = i + 2;
        if (j < NC) {
            const __half* A = (j < 16) ? H1h : H2h;
            const __half* W = (j < 16) ? W1t : W2t;
            const int k0 = (j & 15) * 32;
            load_tile(A + (size_t)(m0 + tid) * NDFF + k0,
                      W + (size_t)nsafe * NDFF + k0,
                      sbase + (uint32_t)(j % NSTAGE) * STAGEB, tid);
        }
        CP_COMMIT();
        const uint32_t st = sbase + (uint32_t)s * STAGEB;
        chunk_mma(st, st + TILEB, mw, nw, lane, acc);
    }

    const float* b1 = p.bC1[zi];
    const float* b2 = p.bC2[zi];
#pragma unroll
    for (int ii = 0; ii < 4; ii++) {
#pragma unroll
        for (int half = 0; half < 2; half++) {
            const int m = m0 + mw + ii * 16 + g + half * 8;
            float* dst = g_mod + (size_t)zi * MDSZ + (size_t)m * ND;
#pragma unroll
            for (int jj = 0; jj < 8; jj++) {
                const int n = n0 + nw + jj * 8 + t * 2;
                if (n < ND)     dst[n]     = acc[ii][jj][half * 2]     + b1[n]     + b2[n];
                if (n + 1 < ND) dst[n + 1] = acc[ii][jj][half * 2 + 1] + b1[n + 1] + b2[n + 1];
            }
        }
    }
}

/* ---------------- attention + residual + LayerNorm ------------------- */
__global__ __launch_bounds__(256)
void attn_ln(const float* __restrict__ X, const float* __restrict__ gamma,
             const float* __restrict__ beta, float* __restrict__ out)
{
    extern __shared__ float zsh[];
    __shared__ float sc[96];
    __shared__ float red[256];

    const int b = blockIdx.x, tid = threadIdx.x;
    const int lane = tid & 31, w = tid >> 5;

    const float* q  = g_qkv +            (size_t)b * NP * ND;
    const float* kx = g_qkv + MDSZ +     (size_t)b * NP * ND;
    const float* v  = g_qkv + 2 * MDSZ + (size_t)b * NP * ND;
    const float* xb = X +                (size_t)b * NP * ND;

    const float scale = rsqrtf((float)ND);
    for (int pr = w; pr < 81; pr += 8) {
        const int i = pr / 9, j = pr % 9;
        const float* qi = q + i * ND;
        const float* kj = kx + j * ND;
        float s = 0.f;
        for (int d = lane; d < ND; d += 32) s = fmaf(qi[d], kj[d], s);
#pragma unroll
        for (int o = 16; o; o >>= 1) s += __shfl_xor_sync(0xffffffffu, s, o);
        if (lane == 0) sc[pr] = s * scale;
    }
    __syncthreads();

    if (tid < 9) {
        float mx = -1e30f;
#pragma unroll
        for (int j = 0; j < 9; j++) mx = fmaxf(mx, sc[tid * 9 + j]);
        float e[9], sum = 0.f;
#pragma unroll
        for (int j = 0; j < 9; j++) { e[j] = expf(sc[tid * 9 + j] - mx); sum += e[j]; }
        const float inv = 1.f / sum;
#pragma unroll
        for (int j = 0; j < 9; j++) sc[tid * 9 + j] = e[j] * inv;
    }
    __syncthreads();

    for (int d = tid; d < ND; d += 256) {
        float vj[9];
#pragma unroll
        for (int j = 0; j < 9; j++) vj[j] = v[j * ND + d];
#pragma unroll
        for (int i = 0; i < 9; i++) {
            float a = xb[i * ND + d];
#pragma unroll
            for (int j = 0; j < 9; j++) a = fmaf(sc[i * 9 + j], vj[j], a);
            zsh[i * ND + d] = a;
        }
    }
    __syncthreads();

    for (int i = 0; i < 9; i++) {
        float s = 0.f;
        for (int d = tid; d < ND; d += 256) s += zsh[i * ND + d];
        red[tid] = s; __syncthreads();
        for (int o = 128; o > 0; o >>= 1) { if (tid < o) red[tid] += red[tid + o]; __syncthreads(); }
        const float mu = red[0] * (1.f / ND);
        __syncthreads();

        float s2 = 0.f;
        for (int d = tid; d < ND; d += 256) { const float tt = zsh[i * ND + d] - mu; s2 = fmaf(tt, tt, s2); }
        red[tid] = s2; __syncthreads();
        for (int o = 128; o > 0; o >>= 1) { if (tid < o) red[tid] += red[tid + o]; __syncthreads(); }
        const float rstd = rsqrtf(red[0] * (1.f / ND) + TEPS);
        __syncthreads();

        float* op = out + ((size_t)b * NP + i) * ND;
        for (int d = tid; d < ND; d += 256)
            op[d] = (zsh[i * ND + d] - mu) * rstd * gamma[d] + beta[d];
    }
}

/* ---------------- launch ---------------- */
extern "C" void kernel_launch(void* const* d_in, const int* in_sizes, int n_in,
                              void* d_out, int out_size)
{
    const float* state = (const float*)d_in[0];
    const float* H1    = (const float*)d_in[1];
    const float* H2    = (const float*)d_in[2];

    MainP mp;
    mp.W[0] = (const float*)d_in[3];  mp.bias[0] = (const float*)d_in[4];
    mp.W[1] = (const float*)d_in[5];  mp.bias[1] = (const float*)d_in[6];
    mp.W[2] = (const float*)d_in[7];  mp.bias[2] = (const float*)d_in[8];

    AuxP ap;
    ap.WC1[0] = (const float*)d_in[9];  ap.bC1[0] = (const float*)d_in[10];
    ap.WC1[1] = (const float*)d_in[11]; ap.bC1[1] = (const float*)d_in[12];
    ap.WC1[2] = (const float*)d_in[13]; ap.bC1[2] = (const float*)d_in[14];
    ap.WC2[0] = (const float*)d_in[15]; ap.bC2[0] = (const float*)d_in[16];
    ap.WC2[1] = (const float*)d_in[17]; ap.bC2[1] = (const float*)d_in[18];
    ap.WC2[2] = (const float*)d_in[19]; ap.bC2[2] = (const float*)d_in[20];

    const float* gamma = (const float*)d_in[21];
    const float* beta  = (const float*)d_in[22];

    __half *xh, *h1h, *h2h, *wth, *wcth;
    cudaGetSymbolAddress((void**)&xh,   g_Xh);
    cudaGetSymbolAddress((void**)&h1h,  g_H1h);
    cudaGetSymbolAddress((void**)&h2h,  g_H2h);
    cudaGetSymbolAddress((void**)&wth,  g_Wth);
    cudaGetSymbolAddress((void**)&wcth, g_WCth);

    cudaFuncSetAttribute(aux_tc,  cudaFuncAttributeMaxDynamicSharedMemorySize, SMEM_BYTES);
    cudaFuncSetAttribute(main_tc, cudaFuncAttributeMaxDynamicSharedMemorySize, SMEM_BYTES);

    dim3 grid((ND + 127) / 128, NM / 128, 3);       /* 22 x 72 x 3 */

    /* L0: all activations -> fp16 (z: X, H1, H2) */
    {
        const int nbX = NM * (NDP / 8);
        dim3 g((nbX + 255) / 256, 1, 3);
        prep_act<<<g, 256>>>(state, H1, H2, xh, h1h, h2h);
    }
    /* L1: all weight transposes (z: 3x W, 6x WC) */
    {
        TransP tp;
        tp.src[0] = mp.W[0];   tp.src[1] = mp.W[1];   tp.src[2] = mp.W[2];
        tp.src[3] = ap.WC1[0]; tp.src[4] = ap.WC1[1]; tp.src[5] = ap.WC1[2];
        tp.src[6] = ap.WC2[0]; tp.src[7] = ap.WC2[1]; tp.src[8] = ap.WC2[2];
        dim3 blkT(32, 8);
        dim3 g((ND + 31) / 32, NDP / 32, 9);
        trans_all<<<g, blkT>>>(tp, wth, wcth);
    }
    /* L2: aux GEMM */
    aux_tc<<<grid, 128, SMEM_BYTES>>>(h1h, h2h, wcth, ap);
    /* L3: main GEMM (profiled slot) */
    main_tc<<<grid, 128, SMEM_BYTES>>>(xh, wth, mp);
    /* L4: attention + LN */
    const size_t sh = (size_t)NP * ND * sizeof(float);
    cudaFuncSetAttribute(attn_ln, cudaFuncAttributeMaxDynamicSharedMemorySize, (int)sh);
    attn_ln<<<NB, 256, sh>>>(state, gamma, beta, (float*)d_out);
}

// round 10
// speedup vs baseline: 1.5747x; 1.5747x over previous
#include <cuda_runtime.h>
#include <cuda_fp16.h>
#include <cstdint>

#define NB   1024
#define NP   9
#define ND   2700
#define NDK  2752                /* ND padded to 64-multiple (43 stages) */
#define NDFF 512
#define NM   (NB * NP)
#define TEPS 1e-5f
#define MDSZ ((size_t)NM * (size_t)ND)

/* ---------------- scratch (device statics; no allocs) ---------------- */
__device__ float  g_mod[3ULL * NM * ND];
__device__ float  g_qkv[3ULL * NM * ND];
__device__ __half g_Xh [(size_t)NM * NDK];     /* X -> fp16, K-padded        */
__device__ __half g_H1h[(size_t)NM * NDFF];
__device__ __half g_H2h[(size_t)NM * NDFF];
__device__ __half g_Wth[3ULL * ND * NDK];      /* W^T  fp16 (n-major, K-pad) */
__device__ __half g_WCth[6ULL * ND * NDFF];    /* WC^T fp16                  */

struct MainP  { const float* W[3]; const float* bias[3]; };
struct AuxP   { const float* WC1[3]; const float* WC2[3]; const float* bC1[3]; const float* bC2[3]; };
struct TransP { const float* src[9]; };        /* W q,k,v then WC1 q,k,v then WC2 q,k,v */

/* ---------------- helpers ---------------- */
__device__ __forceinline__ uint32_t smem_u32(const void* p) {
    uint32_t a;
    asm("{ .reg .u64 t; cvta.to.shared.u64 t, %1; cvt.u32.u64 %0, t; }" : "=r"(a) : "l"(p));
    return a;
}
__device__ __forceinline__ void cp_async16(uint32_t dst, const void* src) {
    asm volatile("cp.async.cg.shared.global [%0], [%1], 16;"
                 :: "r"(dst), "l"(src) : "memory");
}
#define CP_COMMIT() asm volatile("cp.async.commit_group;" ::: "memory")
#define CP_WAIT0()  asm volatile("cp.async.wait_group 0;" ::: "memory")

#define MMA_F16(c, a0, a1, a2, a3, b0, b1)                                            \
    asm volatile("mma.sync.aligned.m16n8k16.row.col.f32.f16.f16.f32 "                 \
        "{%0,%1,%2,%3}, {%4,%5,%6,%7}, {%8,%9}, {%0,%1,%2,%3};"                       \
        : "+f"((c)[0]), "+f"((c)[1]), "+f"((c)[2]), "+f"((c)[3])                      \
        : "r"(a0), "r"(a1), "r"(a2), "r"(a3), "r"(b0), "r"(b1))

__device__ __forceinline__ void ldsm4(uint32_t& r0, uint32_t& r1, uint32_t& r2,
                                      uint32_t& r3, uint32_t addr) {
    asm volatile("ldmatrix.sync.aligned.m8n8.x4.shared.b16 {%0,%1,%2,%3}, [%4];"
                 : "=r"(r0), "=r"(r1), "=r"(r2), "=r"(r3) : "r"(addr));
}

/* smem tile: 128 rows x 144 B stride (128 B data = 64 halfs + 16 pad).
 * LDSM phases: stride 36 words -> 8-row starts {0,4,..,28} x 4 words = all
 * 32 banks, conflict-free.                                                 */
#define ROWB   144
#define TILEB  (128 * ROWB)              /* 18432 B                */
#define STAGEB (2 * TILEB)               /* A + B: 36864 B         */
#define NSTAGE 2
#define SMEM_BYTES (NSTAGE * STAGEB)     /* 73728 B                */

/* ================= prep kernels (2 launches) ================= */
/* z=0: X (pad ND->NDK), z=1: H1, z=2: H2 */
__global__ void prep_act(const float* __restrict__ X, const float* __restrict__ H1,
                         const float* __restrict__ H2, __half* __restrict__ xh,
                         __half* __restrict__ h1h, __half* __restrict__ h2h)
{
    const int z = blockIdx.z;
    const float* in; __half* out; int C, CP;
    if (z == 0)      { in = X;  out = xh;  C = ND;   CP = NDK;  }
    else if (z == 1) { in = H1; out = h1h; C = NDFF; CP = NDFF; }
    else             { in = H2; out = h2h; C = NDFF; CP = NDFF; }
    const int nb = CP / 8;
    const int idx = blockIdx.x * blockDim.x + threadIdx.x;
    if (idx >= NM * nb) return;
    const int row = idx / nb, c0 = (idx % nb) * 8;
    const float* ip = in + (size_t)row * C + c0;
    __half h[8];
    if (c0 + 8 <= C) {
        const float4 v0 = *(const float4*)ip;
        const float4 v1 = *(const float4*)(ip + 4);
        h[0] = __float2half_rn(v0.x); h[1] = __float2half_rn(v0.y);
        h[2] = __float2half_rn(v0.z); h[3] = __float2half_rn(v0.w);
        h[4] = __float2half_rn(v1.x); h[5] = __float2half_rn(v1.y);
        h[6] = __float2half_rn(v1.z); h[7] = __float2half_rn(v1.w);
    } else {
#pragma unroll
        for (int q = 0; q < 8; q++)
            h[q] = (c0 + q < C) ? __float2half_rn(ip[q]) : __float2half_rn(0.f);
    }
    *(uint4*)(out + (size_t)row * CP + c0) = *(const uint4*)h;
}

/* transpose + fp16: z<3: W (2700x2700 -> 2700x2752); z>=3: WC (512x2700 -> 2700x512) */
__global__ void trans_all(TransP tp, __half* __restrict__ wth, __half* __restrict__ wcth)
{
    __shared__ float t[32][33];
    const int z = blockIdx.z;
    int R, RP; __half* dst;
    if (z < 3) { R = ND;   RP = NDK;  dst = wth  + (size_t)z * ND * NDK; }
    else       { R = NDFF; RP = NDFF; dst = wcth + (size_t)(z - 3) * ND * NDFF; }
    const int r0 = blockIdx.y * 32;
    if (r0 >= R) return;
    const float* src = tp.src[z];
    const int c0 = blockIdx.x * 32;
    const int x = threadIdx.x, y = threadIdx.y;    /* 32 x 8 */
#pragma unroll
    for (int yy = y; yy < 32; yy += 8) {
        const int r = r0 + yy, c = c0 + x;
        t[yy][x] = (r < R && c < ND) ? src[(size_t)r * ND + c] : 0.f;
    }
    __syncthreads();
#pragma unroll
    for (int yy = y; yy < 32; yy += 8) {
        const int c = c0 + yy;
        if (c < ND && r0 + x < R)
            dst[(size_t)c * RP + r0 + x] = __float2half_rn(t[x][yy]);
    }
}

/* ================= GEMM mainloop pieces ================= */
/* Coalesced K=64 stage loader: lanes 0..7 read consecutive 16B of ONE row
 * (one 128B line); thread tid covers rows tid/8 + 16j at column (tid%8)*16B.
 * A rows: m0 + r (always valid). B rows: n0 + r clamped to ND-1 (masked in
 * epilogue).                                                               */
__device__ __forceinline__ void load_stage(const __half* Abase, size_t strideA,
                                           const __half* Bbase, size_t strideB,
                                           int n0, int nmax, uint32_t stage, int tid)
{
    const int r0 = tid >> 3;
    const uint32_t cb = (uint32_t)(tid & 7) * 16u;
    const uint32_t sa = stage + (uint32_t)r0 * ROWB + cb;
#pragma unroll
    for (int j = 0; j < 8; j++) {
        const int r = r0 + 16 * j;
        cp_async16(sa + j * (16 * ROWB),
                   (const char*)(Abase + (size_t)r * strideA) + cb);
        int br = n0 + r; if (br > nmax) br = nmax;
        cp_async16(sa + TILEB + j * (16 * ROWB),
                   (const char*)(Bbase + (size_t)(br - n0) * 0 + (size_t)br * strideB) + cb);
    }
}

/* fragment load + MMA for one K=64 stage (4 k-steps of 16).
 * B fragments first (16 regs), A per-ii (4 regs live).                     */
__device__ __forceinline__ void stage_mma(uint32_t aTile, uint32_t bTile,
                                          int mw, int nw, int lane,
                                          float acc[4][8][4])
{
    const uint32_t aBase = aTile +
        (uint32_t)((mw + (lane & 15)) * ROWB + (lane >> 4) * 16);
    const uint32_t bBase = bTile +
        (uint32_t)((nw + (lane & 7) + ((lane & 16) ? 8 : 0)) * ROWB + ((lane >> 3) & 1) * 16);
#pragma unroll
    for (int ks = 0; ks < 4; ks++) {
        uint32_t b[8][2];
#pragma unroll
        for (int jp = 0; jp < 4; jp++)
            ldsm4(b[2 * jp][0], b[2 * jp][1], b[2 * jp + 1][0], b[2 * jp + 1][1],
                  bBase + jp * (16 * ROWB) + ks * 32);
#pragma unroll
        for (int ii = 0; ii < 4; ii++) {
            uint32_t a0, a1, a2, a3;
            ldsm4(a0, a1, a2, a3, aBase + ii * (16 * ROWB) + ks * 32);
#pragma unroll
            for (int jj = 0; jj < 8; jj++)
                MMA_F16(acc[ii][jj], a0, a1, a2, a3, b[jj][0], b[jj][1]);
        }
    }
}

/* ---------------- main GEMM: qkv = (X @ W + b) * mod ----------------- */
__global__ __launch_bounds__(128, 3)
void main_tc(const __half* __restrict__ Xh, const __half* __restrict__ Wall, MainP p)
{
    extern __shared__ __align__(16) uint32_t shu[];
    const uint32_t sbase = smem_u32(shu);
    const int tid = threadIdx.x, lane = tid & 31, wid = tid >> 5;
    const int g = lane >> 2, t = lane & 3;
    const int mw = (wid & 1) * 64, nw = (wid >> 1) * 64;
    const int zi = blockIdx.z, n0 = blockIdx.x * 128, m0 = blockIdx.y * 128;
    const __half* Wt = Wall + (size_t)zi * ND * NDK;
    const int NC = NDK / 64;                     /* 43 */

    float acc[4][8][4];
#pragma unroll
    for (int i = 0; i < 4; i++)
#pragma unroll
        for (int j = 0; j < 8; j++)
#pragma unroll
            for (int q = 0; q < 4; q++) acc[i][j][q] = 0.f;

    /* prologue: stage 0 */
    load_stage(Xh + (size_t)m0 * NDK, NDK, Wt, NDK, n0, ND - 1, sbase, tid);
    CP_COMMIT();

    for (int i = 0; i < NC; i++) {
        CP_WAIT0();
        __syncthreads();
        const int j = i + 1;
        if (j < NC)
            load_stage(Xh + (size_t)m0 * NDK + j * 64, NDK,
                       Wt + (size_t)j * 64, NDK, n0, ND - 1,
                       sbase + (uint32_t)(j & 1) * STAGEB, tid);
        CP_COMMIT();
        const uint32_t st = sbase + (uint32_t)(i & 1) * STAGEB;
        stage_mma(st, st + TILEB, mw, nw, lane, acc);
    }

    const float* bias = p.bias[zi];
#pragma unroll
    for (int ii = 0; ii < 4; ii++) {
#pragma unroll
        for (int half = 0; half < 2; half++) {
            const int m = m0 + mw + ii * 16 + g + half * 8;
            float* dst = g_qkv + (size_t)zi * MDSZ + (size_t)m * ND;
            const float* modp = g_mod + (size_t)zi * MDSZ + (size_t)m * ND;
#pragma unroll
            for (int jj = 0; jj < 8; jj++) {
                const int n = n0 + nw + jj * 8 + t * 2;
                if (n < ND)     dst[n]     = (acc[ii][jj][half * 2]     + bias[n])     * modp[n];
                if (n + 1 < ND) dst[n + 1] = (acc[ii][jj][half * 2 + 1] + bias[n + 1]) * modp[n + 1];
            }
        }
    }
}

/* ---------------- aux GEMM: mod = H1@WC1 + H2@WC2 + bC1 + bC2 -------- */
__global__ __launch_bounds__(128, 3)
void aux_tc(const __half* __restrict__ H1h, const __half* __restrict__ H2h,
            const __half* __restrict__ WCall, AuxP p)
{
    extern __shared__ __align__(16) uint32_t shu[];
    const uint32_t sbase = smem_u32(shu);
    const int tid = threadIdx.x, lane = tid & 31, wid = tid >> 5;
    const int g = lane >> 2, t = lane & 3;
    const int mw = (wid & 1) * 64, nw = (wid >> 1) * 64;
    const int zi = blockIdx.z, n0 = blockIdx.x * 128, m0 = blockIdx.y * 128;
    const __half* W1t = WCall + (size_t)zi * ND * NDFF;
    const __half* W2t = WCall + (size_t)(zi + 3) * ND * NDFF;
    const int NC = 16;                           /* 8 stages per source */

    float acc[4][8][4];
#pragma unroll
    for (int i = 0; i < 4; i++)
#pragma unroll
        for (int j = 0; j < 8; j++)
#pragma unroll
            for (int q = 0; q < 4; q++) acc[i][j][q] = 0.f;

    load_stage(H1h + (size_t)m0 * NDFF, NDFF, W1t, NDFF, n0, ND - 1, sbase, tid);
    CP_COMMIT();

    for (int i = 0; i < NC; i++) {
        CP_WAIT0();
        __syncthreads();
        const int j = i + 1;
        if (j < NC) {
            const __half* A = (j < 8) ? H1h : H2h;
            const __half* W = (j < 8) ? W1t : W2t;
            const int k0 = (j & 7) * 64;
            load_stage(A + (size_t)m0 * NDFF + k0, NDFF,
                       W + (size_t)k0, NDFF, n0, ND - 1,
                       sbase + (uint32_t)(j & 1) * STAGEB, tid);
        }
        CP_COMMIT();
        const uint32_t st = sbase + (uint32_t)(i & 1) * STAGEB;
        stage_mma(st, st + TILEB, mw, nw, lane, acc);
    }

    const float* b1 = p.bC1[zi];
    const float* b2 = p.bC2[zi];
#pragma unroll
    for (int ii = 0; ii < 4; ii++) {
#pragma unroll
        for (int half = 0; half < 2; half++) {
            const int m = m0 + mw + ii * 16 + g + half * 8;
            float* dst = g_mod + (size_t)zi * MDSZ + (size_t)m * ND;
#pragma unroll
            for (int jj = 0; jj < 8; jj++) {
                const int n = n0 + nw + jj * 8 + t * 2;
                if (n < ND)     dst[n]     = acc[ii][jj][half * 2]     + b1[n]     + b2[n];
                if (n + 1 < ND) dst[n + 1] = acc[ii][jj][half * 2 + 1] + b1[n + 1] + b2[n + 1];
            }
        }
    }
}

/* ---------------- attention + residual + LayerNorm ------------------- */
__global__ __launch_bounds__(256)
void attn_ln(const float* __restrict__ X, const float* __restrict__ gamma,
             const float* __restrict__ beta, float* __restrict__ out)
{
    extern __shared__ float zsh[];
    __shared__ float sc[96];
    __shared__ float red[256];

    const int b = blockIdx.x, tid = threadIdx.x;
    const int lane = tid & 31, w = tid >> 5;

    const float* q  = g_qkv +            (size_t)b * NP * ND;
    const float* kx = g_qkv + MDSZ +     (size_t)b * NP * ND;
    const float* v  = g_qkv + 2 * MDSZ + (size_t)b * NP * ND;
    const float* xb = X +                (size_t)b * NP * ND;

    const float scale = rsqrtf((float)ND);
    for (int pr = w; pr < 81; pr += 8) {
        const int i = pr / 9, j = pr % 9;
        const float* qi = q + i * ND;
        const float* kj = kx + j * ND;
        float s = 0.f;
        for (int d = lane; d < ND; d += 32) s = fmaf(qi[d], kj[d], s);
#pragma unroll
        for (int o = 16; o; o >>= 1) s += __shfl_xor_sync(0xffffffffu, s, o);
        if (lane == 0) sc[pr] = s * scale;
    }
    __syncthreads();

    if (tid < 9) {
        float mx = -1e30f;
#pragma unroll
        for (int j = 0; j < 9; j++) mx = fmaxf(mx, sc[tid * 9 + j]);
        float e[9], sum = 0.f;
#pragma unroll
        for (int j = 0; j < 9; j++) { e[j] = expf(sc[tid * 9 + j] - mx); sum += e[j]; }
        const float inv = 1.f / sum;
#pragma unroll
        for (int j = 0; j < 9; j++) sc[tid * 9 + j] = e[j] * inv;
    }
    __syncthreads();

    for (int d = tid; d < ND; d += 256) {
        float vj[9];
#pragma unroll
        for (int j = 0; j < 9; j++) vj[j] = v[j * ND + d];
#pragma unroll
        for (int i = 0; i < 9; i++) {
            float a = xb[i * ND + d];
#pragma unroll
            for (int j = 0; j < 9; j++) a = fmaf(sc[i * 9 + j], vj[j], a);
            zsh[i * ND + d] = a;
        }
    }
    __syncthreads();

    for (int i = 0; i < 9; i++) {
        float s = 0.f;
        for (int d = tid; d < ND; d += 256) s += zsh[i * ND + d];
        red[tid] = s; __syncthreads();
        for (int o = 128; o > 0; o >>= 1) { if (tid < o) red[tid] += red[tid + o]; __syncthreads(); }
        const float mu = red[0] * (1.f / ND);
        __syncthreads();

        float s2 = 0.f;
        for (int d = tid; d < ND; d += 256) { const float tt = zsh[i * ND + d] - mu; s2 = fmaf(tt, tt, s2); }
        red[tid] = s2; __syncthreads();
        for (int o = 128; o > 0; o >>= 1) { if (tid < o) red[tid] += red[tid + o]; __syncthreads(); }
        const float rstd = rsqrtf(red[0] * (1.f / ND) + TEPS);
        __syncthreads();

        float* op = out + ((size_t)b * NP + i) * ND;
        for (int d = tid; d < ND; d += 256)
            op[d] = (zsh[i * ND + d] - mu) * rstd * gamma[d] + beta[d];
    }
}

/* ---------------- launch ---------------- */
extern "C" void kernel_launch(void* const* d_in, const int* in_sizes, int n_in,
                              void* d_out, int out_size)
{
    const float* state = (const float*)d_in[0];
    const float* H1    = (const float*)d_in[1];
    const float* H2    = (const float*)d_in[2];

    MainP mp;
    mp.W[0] = (const float*)d_in[3];  mp.bias[0] = (const float*)d_in[4];
    mp.W[1] = (const float*)d_in[5];  mp.bias[1] = (const float*)d_in[6];
    mp.W[2] = (const float*)d_in[7];  mp.bias[2] = (const float*)d_in[8];

    AuxP ap;
    ap.WC1[0] = (const float*)d_in[9];  ap.bC1[0] = (const float*)d_in[10];
    ap.WC1[1] = (const float*)d_in[11]; ap.bC1[1] = (const float*)d_in[12];
    ap.WC1[2] = (const float*)d_in[13]; ap.bC1[2] = (const float*)d_in[14];
    ap.WC2[0] = (const float*)d_in[15]; ap.bC2[0] = (const float*)d_in[16];
    ap.WC2[1] = (const float*)d_in[17]; ap.bC2[1] = (const float*)d_in[18];
    ap.WC2[2] = (const float*)d_in[19]; ap.bC2[2] = (const float*)d_in[20];

    const float* gamma = (const float*)d_in[21];
    const float* beta  = (const float*)d_in[22];

    __half *xh, *h1h, *h2h, *wth, *wcth;
    cudaGetSymbolAddress((void**)&xh,   g_Xh);
    cudaGetSymbolAddress((void**)&h1h,  g_H1h);
    cudaGetSymbolAddress((void**)&h2h,  g_H2h);
    cudaGetSymbolAddress((void**)&wth,  g_Wth);
    cudaGetSymbolAddress((void**)&wcth, g_WCth);

    cudaFuncSetAttribute(aux_tc,  cudaFuncAttributeMaxDynamicSharedMemorySize, SMEM_BYTES);
    cudaFuncSetAttribute(main_tc, cudaFuncAttributeMaxDynamicSharedMemorySize, SMEM_BYTES);

    dim3 grid((ND + 127) / 128, NM / 128, 3);       /* 22 x 72 x 3 */

    /* L0: all activations -> fp16 (z: X, H1, H2) */
    {
        const int nbX = NM * (NDK / 8);
        dim3 g((nbX + 255) / 256, 1, 3);
        prep_act<<<g, 256>>>(state, H1, H2, xh, h1h, h2h);
    }
    /* L1: all weight transposes (z: 3x W, 6x WC) */
    {
        TransP tp;
        tp.src[0] = mp.W[0];   tp.src[1] = mp.W[1];   tp.src[2] = mp.W[2];
        tp.src[3] = ap.WC1[0]; tp.src[4] = ap.WC1[1]; tp.src[5] = ap.WC1[2];
        tp.src[6] = ap.WC2[0]; tp.src[7] = ap.WC2[1]; tp.src[8] = ap.WC2[2];
        dim3 blkT(32, 8);
        dim3 g((ND + 31) / 32, NDK / 32, 9);
        trans_all<<<g, blkT>>>(tp, wth, wcth);
    }
    /* L2: aux GEMM */
    aux_tc<<<grid, 128, SMEM_BYTES>>>(h1h, h2h, wcth, ap);
    /* L3: main GEMM (profiled slot) */
    main_tc<<<grid, 128, SMEM_BYTES>>>(xh, wth, mp);
    /* L4: attention + LN */
    const size_t sh = (size_t)NP * ND * sizeof(float);
    cudaFuncSetAttribute(attn_ln, cudaFuncAttributeMaxDynamicSharedMemorySize, (int)sh);
    attn_ln<<<NB, 256, sh>>>(state, gamma, beta, (float*)d_out);
}

// round 15
// speedup vs baseline: 1.6136x; 1.0247x over previous
#include <cuda_runtime.h>
#include <cuda_fp16.h>
#include <cstdint>

#define NB   1024
#define NP   9
#define ND   2700
#define NDK  2752                /* ND padded to 64-multiple (43 stages) */
#define NDFF 512
#define NM   (NB * NP)
#define TEPS 1e-5f
#define MDSZ ((size_t)NM * (size_t)ND)

/* ---------------- scratch (device statics; no allocs) ---------------- */
__device__ float  g_mod[3ULL * NM * ND];
__device__ float  g_qkv[3ULL * NM * ND];
__device__ __half g_Xh [(size_t)NM * NDK];     /* X -> fp16, K-padded        */
__device__ __half g_H1h[(size_t)NM * NDFF];
__device__ __half g_H2h[(size_t)NM * NDFF];
__device__ __half g_Wth[3ULL * ND * NDK];      /* W^T  fp16 (n-major, K-pad) */
__device__ __half g_WCth[6ULL * ND * NDFF];    /* WC^T fp16                  */

struct MainP  { const float* W[3]; const float* bias[3]; };
struct AuxP   { const float* WC1[3]; const float* WC2[3]; const float* bC1[3]; const float* bC2[3]; };
struct TransP { const float* src[9]; };        /* W q,k,v then WC1 q,k,v then WC2 q,k,v */

/* ---------------- helpers ---------------- */
__device__ __forceinline__ uint32_t smem_u32(const void* p) {
    uint32_t a;
    asm("{ .reg .u64 t; cvta.to.shared.u64 t, %1; cvt.u32.u64 %0, t; }" : "=r"(a) : "l"(p));
    return a;
}
__device__ __forceinline__ void cp_async16(uint32_t dst, const void* src) {
    asm volatile("cp.async.cg.shared.global [%0], [%1], 16;"
                 :: "r"(dst), "l"(src) : "memory");
}
#define CP_COMMIT() asm volatile("cp.async.commit_group;" ::: "memory")
#define CP_WAIT0()  asm volatile("cp.async.wait_group 0;" ::: "memory")

#define MMA_F16(c, a0, a1, a2, a3, b0, b1)                                            \
    asm volatile("mma.sync.aligned.m16n8k16.row.col.f32.f16.f16.f32 "                 \
        "{%0,%1,%2,%3}, {%4,%5,%6,%7}, {%8,%9}, {%0,%1,%2,%3};"                       \
        : "+f"((c)[0]), "+f"((c)[1]), "+f"((c)[2]), "+f"((c)[3])                      \
        : "r"(a0), "r"(a1), "r"(a2), "r"(a3), "r"(b0), "r"(b1))

__device__ __forceinline__ void ldsm4(uint32_t& r0, uint32_t& r1, uint32_t& r2,
                                      uint32_t& r3, uint32_t addr) {
    asm volatile("ldmatrix.sync.aligned.m8n8.x4.shared.b16 {%0,%1,%2,%3}, [%4];"
                 : "=r"(r0), "=r"(r1), "=r"(r2), "=r"(r3) : "r"(addr));
}

/* smem tile: 128 rows x 144 B stride (128 B data = 64 halfs + 16 pad). */
#define ROWB   144
#define TILEB  (128 * ROWB)              /* 18432 B                */
#define STAGEB (2 * TILEB)               /* A + B: 36864 B         */
#define NSTAGE 2
#define SMEM_BYTES (NSTAGE * STAGEB)     /* 73728 B                */

/* ================= prep kernels (2 launches) ================= */
__global__ void prep_act(const float* __restrict__ X, const float* __restrict__ H1,
                         const float* __restrict__ H2, __half* __restrict__ xh,
                         __half* __restrict__ h1h, __half* __restrict__ h2h)
{
    const int z = blockIdx.z;
    const float* in; __half* out; int C, CP;
    if (z == 0)      { in = X;  out = xh;  C = ND;   CP = NDK;  }
    else if (z == 1) { in = H1; out = h1h; C = NDFF; CP = NDFF; }
    else             { in = H2; out = h2h; C = NDFF; CP = NDFF; }
    const int nb = CP / 8;
    const int idx = blockIdx.x * blockDim.x + threadIdx.x;
    if (idx >= NM * nb) return;
    const int row = idx / nb, c0 = (idx % nb) * 8;
    const float* ip = in + (size_t)row * C + c0;
    __half h[8];
    if (c0 + 8 <= C) {
        const float4 v0 = *(const float4*)ip;
        const float4 v1 = *(const float4*)(ip + 4);
        h[0] = __float2half_rn(v0.x); h[1] = __float2half_rn(v0.y);
        h[2] = __float2half_rn(v0.z); h[3] = __float2half_rn(v0.w);
        h[4] = __float2half_rn(v1.x); h[5] = __float2half_rn(v1.y);
        h[6] = __float2half_rn(v1.z); h[7] = __float2half_rn(v1.w);
    } else {
#pragma unroll
        for (int q = 0; q < 8; q++)
            h[q] = (c0 + q < C) ? __float2half_rn(ip[q]) : __float2half_rn(0.f);
    }
    *(uint4*)(out + (size_t)row * CP + c0) = *(const uint4*)h;
}

__global__ void trans_all(TransP tp, __half* __restrict__ wth, __half* __restrict__ wcth)
{
    __shared__ float t[32][33];
    const int z = blockIdx.z;
    int R, RP; __half* dst;
    if (z < 3) { R = ND;   RP = NDK;  dst = wth  + (size_t)z * ND * NDK; }
    else       { R = NDFF; RP = NDFF; dst = wcth + (size_t)(z - 3) * ND * NDFF; }
    const int r0 = blockIdx.y * 32;
    if (r0 >= R) return;
    const float* src = tp.src[z];
    const int c0 = blockIdx.x * 32;
    const int x = threadIdx.x, y = threadIdx.y;    /* 32 x 8 */
#pragma unroll
    for (int yy = y; yy < 32; yy += 8) {
        const int r = r0 + yy, c = c0 + x;
        t[yy][x] = (r < R && c < ND) ? src[(size_t)r * ND + c] : 0.f;
    }
    __syncthreads();
#pragma unroll
    for (int yy = y; yy < 32; yy += 8) {
        const int c = c0 + yy;
        if (c < ND && r0 + x < R)
            dst[(size_t)c * RP + r0 + x] = __float2half_rn(t[x][yy]);
    }
}

/* ================= GEMM mainloop pieces ================= */
/* Coalesced K=64 stage loader: lanes 0..7 read consecutive 16B of ONE row. */
__device__ __forceinline__ void load_stage(const __half* Abase, size_t strideA,
                                           const __half* Bbase, size_t strideB,
                                           int n0, int nmax, uint32_t stage, int tid)
{
    const int r0 = tid >> 3;
    const uint32_t cb = (uint32_t)(tid & 7) * 16u;
    const uint32_t sa = stage + (uint32_t)r0 * ROWB + cb;
#pragma unroll
    for (int j = 0; j < 8; j++) {
        const int r = r0 + 16 * j;
        cp_async16(sa + j * (16 * ROWB),
                   (const char*)(Abase + (size_t)r * strideA) + cb);
        int br = n0 + r; if (br > nmax) br = nmax;
        cp_async16(sa + TILEB + j * (16 * ROWB),
                   (const char*)(Bbase + (size_t)br * strideB) + cb);
    }
}

/* fragment load + MMA for one K=64 stage (4 k-steps of 16). */
__device__ __forceinline__ void stage_mma(uint32_t aTile, uint32_t bTile,
                                          int mw, int nw, int lane,
                                          float acc[4][8][4])
{
    const uint32_t aBase = aTile +
        (uint32_t)((mw + (lane & 15)) * ROWB + (lane >> 4) * 16);
    const uint32_t bBase = bTile +
        (uint32_t)((nw + (lane & 7) + ((lane & 16) ? 8 : 0)) * ROWB + ((lane >> 3) & 1) * 16);
#pragma unroll
    for (int ks = 0; ks < 4; ks++) {
        uint32_t b[8][2];
#pragma unroll
        for (int jp = 0; jp < 4; jp++)
            ldsm4(b[2 * jp][0], b[2 * jp][1], b[2 * jp + 1][0], b[2 * jp + 1][1],
                  bBase + jp * (16 * ROWB) + ks * 32);
#pragma unroll
        for (int ii = 0; ii < 4; ii++) {
            uint32_t a0, a1, a2, a3;
            ldsm4(a0, a1, a2, a3, aBase + ii * (16 * ROWB) + ks * 32);
#pragma unroll
            for (int jj = 0; jj < 8; jj++)
                MMA_F16(acc[ii][jj], a0, a1, a2, a3, b[jj][0], b[jj][1]);
        }
    }
}

/* ---------------- main GEMM: qkv = (X @ W + b) * mod ----------------- */
__global__ __launch_bounds__(128, 3)
void main_tc(const __half* __restrict__ Xh, const __half* __restrict__ Wall, MainP p)
{
    extern __shared__ __align__(16) uint32_t shu[];
    const uint32_t sbase = smem_u32(shu);
    const int tid = threadIdx.x, lane = tid & 31, wid = tid >> 5;
    const int g = lane >> 2, t = lane & 3;
    const int mw = (wid & 1) * 64, nw = (wid >> 1) * 64;
    const int zi = blockIdx.z, n0 = blockIdx.x * 128, m0 = blockIdx.y * 128;
    const __half* Wt = Wall + (size_t)zi * ND * NDK;
    const int NC = NDK / 64;                     /* 43 */

    float acc[4][8][4];
#pragma unroll
    for (int i = 0; i < 4; i++)
#pragma unroll
        for (int j = 0; j < 8; j++)
#pragma unroll
            for (int q = 0; q < 4; q++) acc[i][j][q] = 0.f;

    /* prologue: stage 0 */
    load_stage(Xh + (size_t)m0 * NDK, NDK, Wt, NDK, n0, ND - 1, sbase, tid);
    CP_COMMIT();

    /* R10-verified ordering: wait -> sync -> prefetch -> commit -> compute.
     * wait BEFORE sync is load-bearing: cp.async completion is per-thread;
     * the barrier after the wait makes every thread's fills CTA-visible.   */
    for (int i = 0; i < NC; i++) {
        CP_WAIT0();
        __syncthreads();
        const int j = i + 1;
        if (j < NC)
            load_stage(Xh + (size_t)m0 * NDK + j * 64, NDK,
                       Wt + (size_t)j * 64, NDK, n0, ND - 1,
                       sbase + (uint32_t)(j & 1) * STAGEB, tid);
        CP_COMMIT();
        const uint32_t st = sbase + (uint32_t)(i & 1) * STAGEB;
        stage_mma(st, st + TILEB, mw, nw, lane, acc);
    }

    const float* bias = p.bias[zi];
#pragma unroll
    for (int ii = 0; ii < 4; ii++) {
#pragma unroll
        for (int half = 0; half < 2; half++) {
            const int m = m0 + mw + ii * 16 + g + half * 8;
            float* dst = g_qkv + (size_t)zi * MDSZ + (size_t)m * ND;
            const float* modp = g_mod + (size_t)zi * MDSZ + (size_t)m * ND;
#pragma unroll
            for (int jj = 0; jj < 8; jj++) {
                const int n = n0 + nw + jj * 8 + t * 2;
                if (n < ND)     dst[n]     = (acc[ii][jj][half * 2]     + bias[n])     * modp[n];
                if (n + 1 < ND) dst[n + 1] = (acc[ii][jj][half * 2 + 1] + bias[n + 1]) * modp[n + 1];
            }
        }
    }
}

/* ---------------- aux GEMM: mod = H1@WC1 + H2@WC2 + bC1 + bC2 -------- */
__global__ __launch_bounds__(128, 3)
void aux_tc(const __half* __restrict__ H1h, const __half* __restrict__ H2h,
            const __half* __restrict__ WCall, AuxP p)
{
    extern __shared__ __align__(16) uint32_t shu[];
    const uint32_t sbase = smem_u32(shu);
    const int tid = threadIdx.x, lane = tid & 31, wid = tid >> 5;
    const int g = lane >> 2, t = lane & 3;
    const int mw = (wid & 1) * 64, nw = (wid >> 1) * 64;
    const int zi = blockIdx.z, n0 = blockIdx.x * 128, m0 = blockIdx.y * 128;
    const __half* W1t = WCall + (size_t)zi * ND * NDFF;
    const __half* W2t = WCall + (size_t)(zi + 3) * ND * NDFF;
    const int NC = 16;                           /* 8 stages per source */

    float acc[4][8][4];
#pragma unroll
    for (int i = 0; i < 4; i++)
#pragma unroll
        for (int j = 0; j < 8; j++)
#pragma unroll
            for (int q = 0; q < 4; q++) acc[i][j][q] = 0.f;

    load_stage(H1h + (size_t)m0 * NDFF, NDFF, W1t, NDFF, n0, ND - 1, sbase, tid);
    CP_COMMIT();

    for (int i = 0; i < NC; i++) {
        CP_WAIT0();
        __syncthreads();
        const int j = i + 1;
        if (j < NC) {
            const __half* A = (j < 8) ? H1h : H2h;
            const __half* W = (j < 8) ? W1t : W2t;
            const int k0 = (j & 7) * 64;
            load_stage(A + (size_t)m0 * NDFF + k0, NDFF,
                       W + (size_t)k0, NDFF, n0, ND - 1,
                       sbase + (uint32_t)(j & 1) * STAGEB, tid);
        }
        CP_COMMIT();
        const uint32_t st = sbase + (uint32_t)(i & 1) * STAGEB;
        stage_mma(st, st + TILEB, mw, nw, lane, acc);
    }

    const float* b1 = p.bC1[zi];
    const float* b2 = p.bC2[zi];
#pragma unroll
    for (int ii = 0; ii < 4; ii++) {
#pragma unroll
        for (int half = 0; half < 2; half++) {
            const int m = m0 + mw + ii * 16 + g + half * 8;
            float* dst = g_mod + (size_t)zi * MDSZ + (size_t)m * ND;
#pragma unroll
            for (int jj = 0; jj < 8; jj++) {
                const int n = n0 + nw + jj * 8 + t * 2;
                if (n < ND)     dst[n]     = acc[ii][jj][half * 2]     + b1[n]     + b2[n];
                if (n + 1 < ND) dst[n + 1] = acc[ii][jj][half * 2 + 1] + b1[n + 1] + b2[n + 1];
            }
        }
    }
}

/* ---------------- attention + residual + LayerNorm ------------------- */
/* scores phase stages q,k chunks in smem (reuses zsh region, which is only
 * live after scores). 3 chunks of 900 floats/row: 2*9*900*4 = 64800 B.    */
#define SCH   900
#define SCH4  (SCH / 4)                  /* 225 float4 per row */
__global__ __launch_bounds__(256)
void attn_ln(const float* __restrict__ X, const float* __restrict__ gamma,
             const float* __restrict__ beta, float* __restrict__ out)
{
    extern __shared__ float zsh[];       /* 24300 floats; first 16200 = q/k chunk */
    __shared__ float sc[96];
    __shared__ float red[256];

    const int b = blockIdx.x, tid = threadIdx.x;
    const int lane = tid & 31, w = tid >> 5;

    const float* q  = g_qkv +            (size_t)b * NP * ND;
    const float* kx = g_qkv + MDSZ +     (size_t)b * NP * ND;
    const float* v  = g_qkv + 2 * MDSZ + (size_t)b * NP * ND;
    const float* xb = X +                (size_t)b * NP * ND;

    /* ---- scores: chunked smem staging, per-warp register partials ---- */
    float4* sq = (float4*)zsh;                   /* 9 x SCH4 */
    float4* sk = (float4*)zsh + 9 * SCH4;
    float ps[11];
#pragma unroll
    for (int u = 0; u < 11; u++) ps[u] = 0.f;

    for (int c = 0; c < ND / SCH; c++) {
        for (int idx = tid; idx < 9 * SCH4; idx += 256) {
            const int row = idx / SCH4, col = idx % SCH4;
            sq[row * SCH4 + col] = *(const float4*)(q  + row * ND + c * SCH + col * 4);
            sk[row * SCH4 + col] = *(const float4*)(kx + row * ND + c * SCH + col * 4);
        }
        __syncthreads();
        int np = 0;
        for (int pr = w; pr < 81; pr += 8, np++) {
            const float4* qa = sq + (pr / 9) * SCH4;
            const float4* kb = sk + (pr % 9) * SCH4;
            float s = ps[np];
            for (int it = lane; it < SCH4; it += 32) {
                const float4 a = qa[it], bb = kb[it];
                s = fmaf(a.x, bb.x, s); s = fmaf(a.y, bb.y, s);
                s = fmaf(a.z, bb.z, s); s = fmaf(a.w, bb.w, s);
            }
            ps[np] = s;
        }
        __syncthreads();
    }
    {
        const float scale = rsqrtf((float)ND);
        int np = 0;
        for (int pr = w; pr < 81; pr += 8, np++) {
            float s = ps[np];
#pragma unroll
            for (int o = 16; o; o >>= 1) s += __shfl_xor_sync(0xffffffffu, s, o);
            if (lane == 0) sc[pr] = s * scale;
        }
    }
    __syncthreads();

    /* ---- softmax ---- */
    if (tid < 9) {
        float mx = -1e30f;
#pragma unroll
        for (int j = 0; j < 9; j++) mx = fmaxf(mx, sc[tid * 9 + j]);
        float e[9], sum = 0.f;
#pragma unroll
        for (int j = 0; j < 9; j++) { e[j] = expf(sc[tid * 9 + j] - mx); sum += e[j]; }
        const float inv = 1.f / sum;
#pragma unroll
        for (int j = 0; j < 9; j++) sc[tid * 9 + j] = e[j] * inv;
    }
    __syncthreads();

    /* ---- attn + residual into zsh (overwrites q/k staging) ---- */
    for (int d = tid; d < ND; d += 256) {
        float vj[9];
#pragma unroll
        for (int j = 0; j < 9; j++) vj[j] = v[j * ND + d];
#pragma unroll
        for (int i = 0; i < 9; i++) {
            float a = xb[i * ND + d];
#pragma unroll
            for (int j = 0; j < 9; j++) a = fmaf(sc[i * 9 + j], vj[j], a);
            zsh[i * ND + d] = a;
        }
    }
    __syncthreads();

    /* ---- per-row two-pass LayerNorm ---- */
    for (int i = 0; i < 9; i++) {
        float s = 0.f;
        for (int d = tid; d < ND; d += 256) s += zsh[i * ND + d];
        red[tid] = s; __syncthreads();
        for (int o = 128; o > 0; o >>= 1) { if (tid < o) red[tid] += red[tid + o]; __syncthreads(); }
        const float mu = red[0] * (1.f / ND);
        __syncthreads();

        float s2 = 0.f;
        for (int d = tid; d < ND; d += 256) { const float tt = zsh[i * ND + d] - mu; s2 = fmaf(tt, tt, s2); }
        red[tid] = s2; __syncthreads();
        for (int o = 128; o > 0; o >>= 1) { if (tid < o) red[tid] += red[tid + o]; __syncthreads(); }
        const float rstd = rsqrtf(red[0] * (1.f / ND) + TEPS);
        __syncthreads();

        float* op = out + ((size_t)b * NP + i) * ND;
        for (int d = tid; d < ND; d += 256)
            op[d] = (zsh[i * ND + d] - mu) * rstd * gamma[d] + beta[d];
    }
}

/* ---------------- launch ---------------- */
extern "C" void kernel_launch(void* const* d_in, const int* in_sizes, int n_in,
                              void* d_out, int out_size)
{
    const float* state = (const float*)d_in[0];
    const float* H1    = (const float*)d_in[1];
    const float* H2    = (const float*)d_in[2];

    MainP mp;
    mp.W[0] = (const float*)d_in[3];  mp.bias[0] = (const float*)d_in[4];
    mp.W[1] = (const float*)d_in[5];  mp.bias[1] = (const float*)d_in[6];
    mp.W[2] = (const float*)d_in[7];  mp.bias[2] = (const float*)d_in[8];

    AuxP ap;
    ap.WC1[0] = (const float*)d_in[9];  ap.bC1[0] = (const float*)d_in[10];
    ap.WC1[1] = (const float*)d_in[11]; ap.bC1[1] = (const float*)d_in[12];
    ap.WC1[2] = (const float*)d_in[13]; ap.bC1[2] = (const float*)d_in[14];
    ap.WC2[0] = (const float*)d_in[15]; ap.bC2[0] = (const float*)d_in[16];
    ap.WC2[1] = (const float*)d_in[17]; ap.bC2[1] = (const float*)d_in[18];
    ap.WC2[2] = (const float*)d_in[19]; ap.bC2[2] = (const float*)d_in[20];

    const float* gamma = (const float*)d_in[21];
    const float* beta  = (const float*)d_in[22];

    __half *xh, *h1h, *h2h, *wth, *wcth;
    cudaGetSymbolAddress((void**)&xh,   g_Xh);
    cudaGetSymbolAddress((void**)&h1h,  g_H1h);
    cudaGetSymbolAddress((void**)&h2h,  g_H2h);
    cudaGetSymbolAddress((void**)&wth,  g_Wth);
    cudaGetSymbolAddress((void**)&wcth, g_WCth);

    cudaFuncSetAttribute(aux_tc,  cudaFuncAttributeMaxDynamicSharedMemorySize, SMEM_BYTES);
    cudaFuncSetAttribute(main_tc, cudaFuncAttributeMaxDynamicSharedMemorySize, SMEM_BYTES);

    dim3 grid((ND + 127) / 128, NM / 128, 3);       /* 22 x 72 x 3 */

    /* L0: all activations -> fp16 (z: X, H1, H2) */
    {
        const int nbX = NM * (NDK / 8);
        dim3 g((nbX + 255) / 256, 1, 3);
        prep_act<<<g, 256>>>(state, H1, H2, xh, h1h, h2h);
    }
    /* L1: all weight transposes (z: 3x W, 6x WC) */
    {
        TransP tp;
        tp.src[0] = mp.W[0];   tp.src[1] = mp.W[1];   tp.src[2] = mp.W[2];
        tp.src[3] = ap.WC1[0]; tp.src[4] = ap.WC1[1]; tp.src[5] = ap.WC1[2];
        tp.src[6] = ap.WC2[0]; tp.src[7] = ap.WC2[1]; tp.src[8] = ap.WC2[2];
        dim3 blkT(32, 8);
        dim3 g((ND + 31) / 32, NDK / 32, 9);
        trans_all<<<g, blkT>>>(tp, wth, wcth);
    }
    /* L2: aux GEMM */
    aux_tc<<<grid, 128, SMEM_BYTES>>>(h1h, h2h, wcth, ap);
    /* L3: main GEMM (profiled slot) */
    main_tc<<<grid, 128, SMEM_BYTES>>>(xh, wth, mp);
    /* L4: attention + LN */
    const size_t sh = (size_t)NP * ND * sizeof(float);
    cudaFuncSetAttribute(attn_ln, cudaFuncAttributeMaxDynamicSharedMemorySize, (int)sh);
    attn_ln<<<NB, 256, sh>>>(state, gamma, beta, (float*)d_out);
}